// round 7
// baseline (speedup 1.0000x reference)
#include <cuda_runtime.h>
#include <cuda_fp16.h>
#include <cstdint>

#define HID 512
#define BATCH 512
#define G4 2048
#define KTOT0 576
#define KTOT1 1024
#define NCH0 9
#define NCH1 16
#define SEQ 128
#define FUT 48
#define TF_DIM 24
#define OUT_DIM 8
#define NSLOT 178           // h0 ring: slot s = h0 state after s inputs

#define CELL_THREADS 256
#define APITCH 144                    // 64 fp16 (128B) + 16B pad
#define A_BYTES (64 * APITCH)         // 9216
#define B_OFF A_BYTES
#define B_BYTES (128 * APITCH)        // 18432
#define STAGE_B (B_OFF + B_BYTES)     // 27648
#define SMEM_B (3 * STAGE_B)          // 82944, 3-stage

// ---------------- persistent device buffers ----------------
__device__ __align__(256) __half g_w0h[G4 * KTOT0];
__device__ __align__(256) __half g_w1h[G4 * KTOT1];
__device__ __align__(256) __half g_xp[SEQ * BATCH * 64];
__device__ __align__(256) __half g_hs[NSLOT][BATCH * HID];  // h0 ring
__device__ __align__(256) __half g_h1[2][BATCH * HID];
__device__ __align__(256) float g_h1f[BATCH * HID];
__device__ __align__(256) float g_c0[BATCH * HID];
__device__ __align__(256) float g_c1[BATCH * HID];
__device__ __align__(256) float g_b0[G4];
__device__ __align__(256) float g_b1[G4];

struct CellArgs {
    const __half* a0slab;   // 64-wide input slab (encoder l0), or null
    const __half* a1;       // h source, chunks (a0?1:0)..+7
    const __half* a2;       // h source, next 8 chunks (l1 only)
    const __half* wh;
    int ktot, nch;
    const float* bias;
    float* cbuf;
    __half* hOut;
    float* hOutF;
    // decode-l0 extras (h1fprev != null => decode l0: build chunk0 via fc)
    const float* h1fprev;
    const float* fcw;
    const float* fcb;
    const float* tfrow;
    float* outrow;
};

// ---------------- PTX helpers ----------------
__device__ __forceinline__ uint32_t smem_u32(const void* p) {
    uint32_t a;
    asm("{ .reg .u64 t; cvta.to.shared.u64 t, %1; cvt.u32.u64 %0, t; }" : "=r"(a) : "l"(p));
    return a;
}
__device__ __forceinline__ void cp16(uint32_t dst, const void* src) {
    asm volatile("cp.async.cg.shared.global [%0], [%1], 16;" :: "r"(dst), "l"(src) : "memory");
}
#define CP_COMMIT() asm volatile("cp.async.commit_group;" ::: "memory")
#define CP_WAIT1()  asm volatile("cp.async.wait_group 1;" ::: "memory")

__device__ __forceinline__ void ldsm4(uint32_t* r, uint32_t addr) {
    asm volatile("ldmatrix.sync.aligned.m8n8.x4.shared.b16 {%0,%1,%2,%3}, [%4];"
                 : "=r"(r[0]), "=r"(r[1]), "=r"(r[2]), "=r"(r[3]) : "r"(addr));
}
__device__ __forceinline__ void mma16816(float* c, const uint32_t* a, const uint32_t* b) {
    asm volatile(
        "mma.sync.aligned.m16n8k16.row.col.f32.f16.f16.f32 "
        "{%0,%1,%2,%3}, {%4,%5,%6,%7}, {%8,%9}, {%0,%1,%2,%3};"
        : "+f"(c[0]), "+f"(c[1]), "+f"(c[2]), "+f"(c[3])
        : "r"(a[0]), "r"(a[1]), "r"(a[2]), "r"(a[3]), "r"(b[0]), "r"(b[1]));
}
__device__ __forceinline__ float sigf(float x) { return 1.0f / (1.0f + __expf(-x)); }

// ---------------- prep kernels ----------------
__global__ void prep_w0(const float* __restrict__ wih, const float* __restrict__ whh) {
    int idx = blockIdx.x * blockDim.x + threadIdx.x;
    if (idx >= G4 * KTOT0) return;
    int n = idx / KTOT0, k = idx - n * KTOT0;
    int row = (n & 3) * HID + (n >> 2);
    float v;
    if (k < 64) v = (k < 32) ? wih[row * 32 + k] : 0.0f;
    else        v = whh[row * HID + (k - 64)];
    g_w0h[idx] = __float2half(v);
}
__global__ void prep_w1(const float* __restrict__ wih, const float* __restrict__ whh) {
    int idx = blockIdx.x * blockDim.x + threadIdx.x;
    if (idx >= G4 * KTOT1) return;
    int n = idx >> 10, k = idx & 1023;
    int row = (n & 3) * HID + (n >> 2);
    float v = (k < HID) ? wih[row * HID + k] : whh[row * HID + (k - HID)];
    g_w1h[idx] = __float2half(v);
}
__global__ void prep_bias(const float* __restrict__ bi0, const float* __restrict__ bh0,
                          const float* __restrict__ bi1, const float* __restrict__ bh1) {
    int n = blockIdx.x * blockDim.x + threadIdx.x;
    if (n >= G4) return;
    int row = (n & 3) * HID + (n >> 2);
    g_b0[n] = bi0[row] + bh0[row];
    g_b1[n] = bi1[row] + bh1[row];
}
__global__ void prep_xpad(const float* __restrict__ x) {
    int idx = blockIdx.x * blockDim.x + threadIdx.x;
    if (idx >= SEQ * BATCH * 64) return;
    int k = idx & 63, bt = idx >> 6;
    g_xp[idx] = __float2half((k < 32) ? x[bt * 32 + k] : 0.0f);
}
__global__ void init_state(const float* __restrict__ h0in, const float* __restrict__ c0in) {
    int idx = blockIdx.x * blockDim.x + threadIdx.x;
    if (idx >= BATCH * HID) return;
    int j = idx & (HID - 1);
    g_hs[0][idx] = __float2half(h0in[j]);
    g_h1[0][idx] = __float2half(h0in[HID + j]);
    g_c0[idx] = c0in[j];
    g_c1[idx] = c0in[HID + j];
}

// ---------------- chunk loader ----------------
__device__ __forceinline__ void load_chunk(
    uint32_t stage, int tid, int c, int m0, int n0,
    const CellArgs& P, bool decode)
{
    const bool skipA = decode && (c == 0);
    if (!skipA) {
        const char* sA;
        size_t pitchA;
        if (c == 0 && P.a0slab != nullptr) {
            sA = (const char*)P.a0slab + (size_t)m0 * 128;
            pitchA = 128;
        } else {
            int s1 = c - ((P.a0slab != nullptr || decode) ? 1 : 0);
            const __half* src = (s1 < 8) ? P.a1 : P.a2;
            if (s1 >= 8) s1 -= 8;
            sA = (const char*)src + (size_t)m0 * 1024 + (size_t)s1 * 128;
            pitchA = 1024;
        }
#pragma unroll
        for (int i = 0; i < 2; ++i) {
            int idx = tid + i * CELL_THREADS;
            int r = idx >> 3, q = idx & 7;
            cp16(stage + r * APITCH + q * 16, sA + (size_t)r * pitchA + q * 16);
        }
    }
    const char* sB = (const char*)P.wh + ((size_t)n0 * P.ktot + (size_t)c * 64) * 2;
    const size_t pitchB = (size_t)P.ktot * 2;
#pragma unroll
    for (int i = 0; i < 4; ++i) {
        int idx = tid + i * CELL_THREADS;
        int r = idx >> 3, q = idx & 7;
        cp16(stage + B_OFF + r * APITCH + q * 16, sB + (size_t)r * pitchB + q * 16);
    }
}

// ---------------- fused LSTM cell (8 warps, 64x128 tile, 3-stage) ----------------
__global__ __launch_bounds__(CELL_THREADS, 2)
void lstm_cell(CellArgs A0, CellArgs A1)
{
    const CellArgs& P = (blockIdx.z == 0) ? A0 : A1;
    extern __shared__ char smem_raw[];
    const uint32_t sb = smem_u32(smem_raw);

    const int tid = threadIdx.x;
    const int l = tid & 31;
    const int w = tid >> 5;
    const int wm = w & 1;          // 0..1 : 32-row slab
    const int wn = w >> 1;         // 0..3 : 32-col slab
    const int n0 = blockIdx.x * 128;
    const int m0 = blockIdx.y * 64;
    const bool decode = (P.h1fprev != nullptr);
    const int nch = P.nch;

    float acc[2][4][4];
#pragma unroll
    for (int mt = 0; mt < 2; ++mt)
#pragma unroll
        for (int nt = 0; nt < 4; ++nt)
#pragma unroll
            for (int i = 0; i < 4; ++i) acc[mt][nt][i] = 0.0f;

    // prologue: chunks 0,1
    load_chunk(sb, tid, 0, m0, n0, P, decode);
    CP_COMMIT();
    load_chunk(sb + STAGE_B, tid, 1, m0, n0, P, decode);
    CP_COMMIT();

    // decode-l0: build chunk-0 A slab in smem: [y(8) | tf(24) | zeros(32)]
    if (decode) {
#pragma unroll
        for (int p2 = 0; p2 < 2; ++p2) {
            int pr = tid + p2 * CELL_THREADS;
            int row = pr >> 3, o = pr & 7;
            const float4* h4 = (const float4*)(P.h1fprev + (size_t)(m0 + row) * HID);
            const float4* w4 = (const float4*)(P.fcw + (size_t)o * HID);
            float s = P.fcb[o];
#pragma unroll 4
            for (int j = 0; j < HID / 4; ++j) {
                float4 a = h4[j], b = w4[j];
                s += a.x * b.x + a.y * b.y + a.z * b.z + a.w * b.w;
            }
            *(__half*)(smem_raw + row * APITCH + o * 2) = __float2half(s);
            if (blockIdx.x == 0)
                P.outrow[(m0 + row) * OUT_DIM + o] = s;
        }
        for (int i = tid; i < 64 * TF_DIM; i += CELL_THREADS) {
            int row = i / TF_DIM, cl = i - row * TF_DIM;
            *(__half*)(smem_raw + row * APITCH + (8 + cl) * 2) =
                __float2half(P.tfrow[(size_t)(m0 + row) * TF_DIM + cl]);
        }
        for (int i = tid; i < 1024; i += CELL_THREADS) {
            int row = i >> 4, c32 = i & 15;
            *(uint32_t*)(smem_raw + row * APITCH + 64 + c32 * 4) = 0u;
        }
    }

    const uint32_t aRow = (uint32_t)(wm * 32 + (l & 15));
    const uint32_t aColB = (uint32_t)((l >> 4) * 16);
    const uint32_t bRow = (uint32_t)(wn * 32 + (l & 7) + ((l >> 4) & 1) * 8);
    const uint32_t bColB = (uint32_t)(((l >> 3) & 1) * 16);

    for (int c = 0; c < nch; ++c) {
        CP_WAIT1();              // oldest outstanding (chunk c) complete
        __syncthreads();         // all warps done with stage (c-1)%3 compute, see chunk c
        if (c + 2 < nch)
            load_chunk(sb + (uint32_t)((c + 2) % 3) * STAGE_B, tid, c + 2, m0, n0, P, decode);
        CP_COMMIT();             // always commit (possibly empty) to keep accounting fixed

        const uint32_t stage = sb + (uint32_t)(c % 3) * STAGE_B;
#pragma unroll
        for (int ks = 0; ks < 4; ++ks) {
            const uint32_t kb = (uint32_t)(ks * 32);
            uint32_t a[2][4];
#pragma unroll
            for (int mt = 0; mt < 2; ++mt)
                ldsm4(a[mt], stage + (aRow + mt * 16) * APITCH + aColB + kb);
            uint32_t b[4][2];
#pragma unroll
            for (int ntp = 0; ntp < 2; ++ntp) {
                uint32_t r4[4];
                ldsm4(r4, stage + B_OFF + (bRow + ntp * 16) * APITCH + bColB + kb);
                b[ntp * 2][0] = r4[0]; b[ntp * 2][1] = r4[1];
                b[ntp * 2 + 1][0] = r4[2]; b[ntp * 2 + 1][1] = r4[3];
            }
#pragma unroll
            for (int mt = 0; mt < 2; ++mt)
#pragma unroll
                for (int nt = 0; nt < 4; ++nt)
                    mma16816(acc[mt][nt], a[mt], b[nt]);
        }
    }

    // ---- epilogue ----
    const bool odd = (l & 1) != 0;
#pragma unroll
    for (int mt = 0; mt < 2; ++mt)
#pragma unroll
        for (int nt = 0; nt < 4; ++nt) {
            float* cc = acc[mt][nt];
            float send1 = odd ? cc[0] : cc[2];
            float send2 = odd ? cc[1] : cc[3];
            float r1 = __shfl_xor_sync(0xffffffffu, send1, 1);
            float r2 = __shfl_xor_sync(0xffffffffu, send2, 1);
            float gi, gf, gg, go;
            if (!odd) { gi = cc[0]; gf = cc[1]; gg = r1; go = r2; }
            else      { gi = r1;    gf = r2;    gg = cc[2]; go = cc[3]; }

            const int j = ((n0 + wn * 32 + nt * 8) >> 2) + ((l & 3) >> 1);
            const float4 b4 = *(const float4*)(P.bias + 4 * j);
            gi += b4.x; gf += b4.y; gg += b4.z; go += b4.w;

            const int bglob = m0 + wm * 32 + mt * 16 + (l >> 2) + (odd ? 8 : 0);
            const int ix = bglob * HID + j;
            float cp = P.cbuf[ix];
            float cn = sigf(gf) * cp + sigf(gi) * tanhf(gg);
            float hn = sigf(go) * tanhf(cn);
            P.cbuf[ix] = cn;
            P.hOut[ix] = __float2half(hn);
            if (P.hOutF != nullptr) P.hOutF[ix] = hn;
        }
}

// ---------------- final output row ----------------
__global__ void fc_out(const float* __restrict__ h1f,
                       const float* __restrict__ fcw, const float* __restrict__ fcb,
                       float* __restrict__ outp) {
    int idx = blockIdx.x * blockDim.x + threadIdx.x;   // 4096
    int b = idx >> 3, o = idx & 7;
    const float4* h4 = (const float4*)(h1f + (size_t)b * HID);
    const float4* w4 = (const float4*)(fcw + (size_t)o * HID);
    float s = fcb[o];
#pragma unroll 4
    for (int j = 0; j < HID / 4; ++j) {
        float4 a = h4[j], w = w4[j];
        s += a.x * w.x + a.y * w.y + a.z * w.z + a.w * w.w;
    }
    outp[b * OUT_DIM + o] = s;
}

// ---------------- host orchestration ----------------
extern "C" void kernel_launch(void* const* d_in, const int* in_sizes, int n_in,
                              void* d_out, int out_size) {
    const float* x     = (const float*)d_in[0];
    const float* ft    = (const float*)d_in[1];
    const float* h0in  = (const float*)d_in[2];
    const float* c0in  = (const float*)d_in[3];
    const float* w_ih0 = (const float*)d_in[4];
    const float* w_hh0 = (const float*)d_in[5];
    const float* b_ih0 = (const float*)d_in[6];
    const float* b_hh0 = (const float*)d_in[7];
    const float* w_ih1 = (const float*)d_in[8];
    const float* w_hh1 = (const float*)d_in[9];
    const float* b_ih1 = (const float*)d_in[10];
    const float* b_hh1 = (const float*)d_in[11];
    const float* fcw   = (const float*)d_in[12];
    const float* fcb   = (const float*)d_in[13];
    float* out = (float*)d_out;

    cudaFuncSetAttribute(lstm_cell, cudaFuncAttributeMaxDynamicSharedMemorySize, SMEM_B);

    __half *w0h, *w1h, *xp, *hs, *h1p;
    float *h1fp, *c0p, *c1p, *b0p, *b1p;
    cudaGetSymbolAddress((void**)&w0h, g_w0h);
    cudaGetSymbolAddress((void**)&w1h, g_w1h);
    cudaGetSymbolAddress((void**)&xp, g_xp);
    cudaGetSymbolAddress((void**)&hs, g_hs);
    cudaGetSymbolAddress((void**)&h1p, g_h1);
    cudaGetSymbolAddress((void**)&h1fp, g_h1f);
    cudaGetSymbolAddress((void**)&c0p, g_c0);  cudaGetSymbolAddress((void**)&c1p, g_c1);
    cudaGetSymbolAddress((void**)&b0p, g_b0);  cudaGetSymbolAddress((void**)&b1p, g_b1);

    prep_w0<<<(G4 * KTOT0 + 255) / 256, 256>>>(w_ih0, w_hh0);
    prep_w1<<<(G4 * KTOT1 + 255) / 256, 256>>>(w_ih1, w_hh1);
    prep_bias<<<(G4 + 255) / 256, 256>>>(b_ih0, b_hh0, b_ih1, b_hh1);
    prep_xpad<<<(SEQ * BATCH * 64 + 255) / 256, 256>>>(x);
    init_state<<<(BATCH * HID + 255) / 256, 256>>>(h0in, c0in);

    const int SN = BATCH * HID;
    auto slot = [&](int s) { return hs + (size_t)s * SN; };

    CellArgs Z = {};  // zeroed dummy

    auto mk_l0enc = [&](int s) {   // l0(s): reads slot[s] + x[s], writes slot[s+1]
        CellArgs a = {};
        a.a0slab = xp + (size_t)s * BATCH * 64;
        a.a1 = slot(s);
        a.wh = w0h; a.ktot = KTOT0; a.nch = NCH0;
        a.bias = b0p; a.cbuf = c0p; a.hOut = slot(s + 1);
        return a;
    };
    auto mk_l1 = [&](int s, int p, float* hf) {  // l1 step s: reads slot[s+1], h1[p]
        CellArgs a = {};
        a.a1 = slot(s + 1);
        a.a2 = h1p + p * SN;
        a.wh = w1h; a.ktot = KTOT1; a.nch = NCH1;
        a.bias = b1p; a.cbuf = c1p; a.hOut = h1p + (p ^ 1) * SN; a.hOutF = hf;
        return a;
    };
    auto mk_l0dec = [&](int d) {   // decode l0 step s=128+d: fc prologue builds input
        CellArgs a = {};
        a.a1 = slot(SEQ + d);
        a.wh = w0h; a.ktot = KTOT0; a.nch = NCH0;
        a.bias = b0p; a.cbuf = c0p; a.hOut = slot(SEQ + d + 1);
        a.h1fprev = h1fp; a.fcw = fcw; a.fcb = fcb;
        a.tfrow = ft + (size_t)d * BATCH * TF_DIM;
        a.outrow = out + (size_t)d * BATCH * OUT_DIM;
        return a;
    };

    int p = 0;
    const dim3 gridS(16, 8, 1), gridC(16, 8, 2);

    // encoder
    lstm_cell<<<gridS, CELL_THREADS, SMEM_B>>>(mk_l0enc(0), Z);
    for (int t = 0; t < SEQ - 1; ++t) {        // combined: l1(t) || l0(t+1)
        lstm_cell<<<gridC, CELL_THREADS, SMEM_B>>>(mk_l1(t, p, nullptr), mk_l0enc(t + 1));
        p ^= 1;
    }
    lstm_cell<<<gridS, CELL_THREADS, SMEM_B>>>(mk_l1(SEQ - 1, p, h1fp), Z);
    p ^= 1;

    // autoregressive decode
    for (int d = 0; d < FUT - 1; ++d) {
        lstm_cell<<<gridS, CELL_THREADS, SMEM_B>>>(mk_l0dec(d), Z);
        lstm_cell<<<gridS, CELL_THREADS, SMEM_B>>>(mk_l1(SEQ + d, p, h1fp), Z);
        p ^= 1;
    }
    fc_out<<<16, 256>>>(h1fp, fcw, fcb, out + (size_t)(FUT - 1) * BATCH * OUT_DIM);
}

// round 8
// speedup vs baseline: 1.2222x; 1.2222x over previous
#include <cuda_runtime.h>
#include <cuda_fp16.h>
#include <cstdint>

#define HID 512
#define BATCH 512
#define G4 2048
#define NCH0 9
#define NCH1 16
#define KTOT0 576
#define KTOT1 1024
#define SEQ 128
#define FUT 48
#define TF_DIM 24
#define OUT_DIM 8

#define CELL_THREADS 512
#define A_TILE_B 8192               // 64 rows x 128B
#define B_TILE_B 16384              // 128 rows x 128B
#define STAGE_B (A_TILE_B + B_TILE_B)   // 24576
#define MBAR_OFF (3 * STAGE_B)          // 73728
#define SMEM_B (MBAR_OFF + 64)
#define CHSLAB 65536                // bytes per (chunk, full-batch) A slab: 512*128

// ---------------- persistent device buffers (all chunk-tiled, pre-swizzled) -------
__device__ __align__(256) __half g_w0[16 * NCH0 * 128 * 64];   // [nblk][chunk][128][64]
__device__ __align__(256) __half g_w1[16 * NCH1 * 128 * 64];
__device__ __align__(256) __half g_xp[SEQ * BATCH * 64];       // [t][b][64] swizzled
__device__ __align__(256) __half g_ip[BATCH * 64];             // decode input slab
__device__ __align__(256) __half g_h0[2][BATCH * HID];         // [8 chunks][512][64] swz
__device__ __align__(256) __half g_h1[2][BATCH * HID];
__device__ __align__(256) float g_h1f[BATCH * HID];            // fp32 h1 (plain) for FC
__device__ __align__(256) float g_c0[BATCH * HID];
__device__ __align__(256) float g_c1[BATCH * HID];
__device__ __align__(256) float g_b0[G4];
__device__ __align__(256) float g_b1[G4];

// ---------------- helpers ----------------
__device__ __forceinline__ int swz(int k, int r) {   // k: 0..63 within chunk, r: row
    return (((k >> 3) ^ (r & 7)) << 3) | (k & 7);
}
__device__ __forceinline__ uint32_t smem_u32(const void* p) {
    uint32_t a;
    asm("{ .reg .u64 t; cvta.to.shared.u64 t, %1; cvt.u32.u64 %0, t; }" : "=r"(a) : "l"(p));
    return a;
}
__device__ __forceinline__ void cpbulk(uint32_t dst, const void* src, uint32_t bytes,
                                       uint32_t mbar) {
    asm volatile(
        "cp.async.bulk.shared::cluster.global.mbarrier::complete_tx::bytes "
        "[%0], [%1], %2, [%3];"
        :: "r"(dst), "l"(src), "r"(bytes), "r"(mbar) : "memory");
}
#define FENCE_ASYNC() asm volatile("fence.proxy.async.shared::cta;" ::: "memory")
#define MBAR_INIT(a, n) asm volatile("mbarrier.init.shared.b64 [%0], %1;" :: "r"(a), "r"(n) : "memory")
#define MBAR_EXPECT_TX(a, tx) asm volatile("mbarrier.arrive.expect_tx.shared.b64 _, [%0], %1;" :: "r"(a), "r"(tx) : "memory")

__device__ __forceinline__ void mbar_wait(uint32_t mbar, uint32_t parity) {
    asm volatile(
        "{\n\t.reg .pred P1;\n\t"
        "WL_%=:\n\t"
        "mbarrier.try_wait.parity.acquire.cta.shared::cta.b64 P1, [%0], %1, 0x989680;\n\t"
        "@P1 bra.uni WD_%=;\n\t"
        "bra.uni WL_%=;\n\t"
        "WD_%=:\n\t}"
        :: "r"(mbar), "r"(parity) : "memory");
}
__device__ __forceinline__ void ldsm4(uint32_t* r, uint32_t addr) {
    asm volatile("ldmatrix.sync.aligned.m8n8.x4.shared.b16 {%0,%1,%2,%3}, [%4];"
                 : "=r"(r[0]), "=r"(r[1]), "=r"(r[2]), "=r"(r[3]) : "r"(addr));
}
__device__ __forceinline__ void mma16816(float* c, const uint32_t* a, const uint32_t* b) {
    asm volatile(
        "mma.sync.aligned.m16n8k16.row.col.f32.f16.f16.f32 "
        "{%0,%1,%2,%3}, {%4,%5,%6,%7}, {%8,%9}, {%0,%1,%2,%3};"
        : "+f"(c[0]), "+f"(c[1]), "+f"(c[2]), "+f"(c[3])
        : "r"(a[0]), "r"(a[1]), "r"(a[2]), "r"(a[3]), "r"(b[0]), "r"(b[1]));
}
__device__ __forceinline__ float sigf(float x) { return 1.0f / (1.0f + __expf(-x)); }

// ---------------- prep kernels ----------------
__global__ void prep_w0(const float* __restrict__ wih, const float* __restrict__ whh) {
    int idx = blockIdx.x * blockDim.x + threadIdx.x;
    if (idx >= G4 * KTOT0) return;
    int n = idx / KTOT0, k = idx - n * KTOT0;
    int row = (n & 3) * HID + (n >> 2);        // gate-interleaved source row
    float v;
    if (k < 64) v = (k < 32) ? wih[row * 32 + k] : 0.0f;
    else        v = whh[row * HID + (k - 64)];
    int r = n & 127;
    size_t dst = ((size_t)((n >> 7) * NCH0 + (k >> 6)) * 128 + r) * 64 + swz(k & 63, r);
    g_w0[dst] = __float2half(v);
}
__global__ void prep_w1(const float* __restrict__ wih, const float* __restrict__ whh) {
    int idx = blockIdx.x * blockDim.x + threadIdx.x;
    if (idx >= G4 * KTOT1) return;
    int n = idx >> 10, k = idx & 1023;
    int row = (n & 3) * HID + (n >> 2);
    float v = (k < HID) ? wih[row * HID + k] : whh[row * HID + (k - HID)];
    int r = n & 127;
    size_t dst = ((size_t)((n >> 7) * NCH1 + (k >> 6)) * 128 + r) * 64 + swz(k & 63, r);
    g_w1[dst] = __float2half(v);
}
__global__ void prep_bias(const float* __restrict__ bi0, const float* __restrict__ bh0,
                          const float* __restrict__ bi1, const float* __restrict__ bh1) {
    int n = blockIdx.x * blockDim.x + threadIdx.x;
    if (n >= G4) return;
    int row = (n & 3) * HID + (n >> 2);
    g_b0[n] = bi0[row] + bh0[row];
    g_b1[n] = bi1[row] + bh1[row];
}
__global__ void prep_xpad(const float* __restrict__ x) {
    int idx = blockIdx.x * blockDim.x + threadIdx.x;
    if (idx >= SEQ * BATCH * 64) return;
    int k = idx & 63, b = (idx >> 6) & 511, t = idx >> 15;
    float v = (k < 32) ? x[((size_t)t * BATCH + b) * 32 + k] : 0.0f;
    g_xp[((size_t)t * BATCH + b) * 64 + swz(k, b)] = __float2half(v);
}
__global__ void prep_ipzero() {
    int idx = blockIdx.x * blockDim.x + threadIdx.x;
    if (idx < BATCH * 64) g_ip[idx] = __float2half(0.0f);
}
__global__ void init_state(const float* __restrict__ h0in, const float* __restrict__ c0in) {
    int idx = blockIdx.x * blockDim.x + threadIdx.x;
    if (idx >= BATCH * HID) return;
    int b = idx >> 9, j = idx & (HID - 1);
    size_t dst = ((size_t)(j >> 6) * BATCH + b) * 64 + swz(j & 63, b);
    g_h0[0][dst] = __float2half(h0in[j]);
    g_h1[0][dst] = __float2half(h0in[HID + j]);
    g_c0[idx] = c0in[j];
    g_c1[idx] = c0in[HID + j];
}

// ---------------- fused LSTM cell (bulk-copy pipeline, 16 warps) ----------------
__global__ __launch_bounds__(CELL_THREADS, 1)
void lstm_cell(const __half* __restrict__ slab0,   // chunk0 A slab (xp row / g_ip) or null
               const __half* __restrict__ a1,      // h chunks (after slab0): 0..7
               const __half* __restrict__ a2,      // h chunks 8..15 (l1)
               const __half* __restrict__ wt,      // weight tiles
               int nch,
               const float* __restrict__ bias,
               float* __restrict__ cbuf,
               __half* __restrict__ hOut,          // chunked-swizzled layout
               float* __restrict__ hOutF)
{
    extern __shared__ char smem_raw[];
    const uint32_t sb = smem_u32(smem_raw);
    const int tid = threadIdx.x;
    const int l = tid & 31, w = tid >> 5;
    const int wm = w & 3;          // 0..3 : 16-row slab
    const int wn = w >> 2;         // 0..3 : 32-col slab
    const int n0 = blockIdx.x * 128;
    const int m0 = blockIdx.y * 64;

    if (tid == 0) {
#pragma unroll
        for (int s = 0; s < 3; ++s) MBAR_INIT(sb + MBAR_OFF + s * 8, 1);
    }
    __syncthreads();

    const char* wbase = (const char*)wt + (size_t)blockIdx.x * nch * B_TILE_B;

    auto issue = [&](int c) {
        const uint32_t st = sb + (uint32_t)(c % 3) * STAGE_B;
        const uint32_t mb = sb + MBAR_OFF + (uint32_t)(c % 3) * 8;
        FENCE_ASYNC();
        MBAR_EXPECT_TX(mb, STAGE_B);
        const char* srcA;
        if (c == 0 && slab0 != nullptr) {
            srcA = (const char*)slab0 + (size_t)m0 * 128;
        } else {
            int s1 = c - (slab0 != nullptr ? 1 : 0);
            const __half* base = (s1 < 8) ? a1 : a2;
            if (s1 >= 8) s1 -= 8;
            srcA = (const char*)base + (size_t)s1 * CHSLAB + (size_t)m0 * 128;
        }
        cpbulk(st, srcA, A_TILE_B, mb);
        cpbulk(st + A_TILE_B, wbase + (size_t)c * B_TILE_B, B_TILE_B, mb);
    };

    if (tid == 0) { issue(0); issue(1); }

    float acc[4][4];
#pragma unroll
    for (int nt = 0; nt < 4; ++nt)
#pragma unroll
        for (int i = 0; i < 4; ++i) acc[nt][i] = 0.0f;

    const uint32_t aRow = (uint32_t)(wm * 16 + (l & 15));
    const uint32_t aQl = (uint32_t)(l >> 4);
    const uint32_t bRowB = (uint32_t)(wn * 32 + (l & 7) + ((l >> 4) & 1) * 8);
    const uint32_t bQl = (uint32_t)((l >> 3) & 1);

    for (int c = 0; c < nch; ++c) {
        if (c > 0) __syncthreads();           // all warps done with stage (c-1)%3
        if (tid == 0 && c + 2 < nch) issue(c + 2);
        mbar_wait(sb + MBAR_OFF + (uint32_t)(c % 3) * 8, (uint32_t)((c / 3) & 1));
        const uint32_t stage = sb + (uint32_t)(c % 3) * STAGE_B;

#pragma unroll
        for (int ks = 0; ks < 4; ++ks) {
            const uint32_t qa = aQl + ks * 2;
            uint32_t a[4];
            ldsm4(a, stage + aRow * 128 + ((qa ^ (aRow & 7)) << 4));
            uint32_t b[4][2];
#pragma unroll
            for (int ntp = 0; ntp < 2; ++ntp) {
                const uint32_t br = bRowB + ntp * 16;
                const uint32_t qb = bQl + ks * 2;
                uint32_t r4[4];
                ldsm4(r4, stage + A_TILE_B + br * 128 + ((qb ^ (br & 7)) << 4));
                b[ntp * 2][0] = r4[0]; b[ntp * 2][1] = r4[1];
                b[ntp * 2 + 1][0] = r4[2]; b[ntp * 2 + 1][1] = r4[3];
            }
#pragma unroll
            for (int nt = 0; nt < 4; ++nt)
                mma16816(acc[nt], a, b[nt]);
        }
    }

    // ---- epilogue: assemble gates via lane-pair exchange, LSTM update ----
    const bool odd = (l & 1) != 0;
#pragma unroll
    for (int nt = 0; nt < 4; ++nt) {
        float* cc = acc[nt];
        float send1 = odd ? cc[0] : cc[2];
        float send2 = odd ? cc[1] : cc[3];
        float r1 = __shfl_xor_sync(0xffffffffu, send1, 1);
        float r2 = __shfl_xor_sync(0xffffffffu, send2, 1);
        float gi, gf, gg, go;
        if (!odd) { gi = cc[0]; gf = cc[1]; gg = r1; go = r2; }
        else      { gi = r1;    gf = r2;    gg = cc[2]; go = cc[3]; }

        const int j = ((n0 + wn * 32 + nt * 8) >> 2) + ((l & 3) >> 1);
        const float4 b4 = *(const float4*)(bias + 4 * j);
        gi += b4.x; gf += b4.y; gg += b4.z; go += b4.w;

        const int bglob = m0 + wm * 16 + (l >> 2) + (odd ? 8 : 0);
        const int ix = bglob * HID + j;
        float cp = cbuf[ix];
        float cn = sigf(gf) * cp + sigf(gi) * tanhf(gg);
        float hn = sigf(go) * tanhf(cn);
        cbuf[ix] = cn;
        hOut[((size_t)(j >> 6) * BATCH + bglob) * 64 + swz(j & 63, bglob)] = __float2half(hn);
        if (hOutF != nullptr) hOutF[ix] = hn;
    }
}

// ---------------- FC head (+ next decode-input packing, swizzled) ----------------
__global__ void fc_head(const float* __restrict__ h1f,
                        const float* __restrict__ fcw, const float* __restrict__ fcb,
                        float* __restrict__ outp, const float* __restrict__ tf) {
    int idx = blockIdx.x * blockDim.x + threadIdx.x;   // 4096 = B*OUT
    int b = idx >> 3, o = idx & 7;
    const float4* h4 = (const float4*)(h1f + (size_t)b * HID);
    const float4* w4 = (const float4*)(fcw + (size_t)o * HID);
    float s = fcb[o];
#pragma unroll 4
    for (int j = 0; j < HID / 4; ++j) {
        float4 a = h4[j], wv = w4[j];
        s += a.x * wv.x + a.y * wv.y + a.z * wv.z + a.w * wv.w;
    }
    outp[b * OUT_DIM + o] = s;
    if (tf != nullptr) {
        g_ip[(size_t)b * 64 + swz(o, b)] = __float2half(s);
#pragma unroll
        for (int m = 0; m < 3; ++m) {
            int kk = 8 + o * 3 + m;
            g_ip[(size_t)b * 64 + swz(kk, b)] =
                __float2half(tf[(size_t)b * TF_DIM + o * 3 + m]);
        }
    }
}

// ---------------- host orchestration ----------------
extern "C" void kernel_launch(void* const* d_in, const int* in_sizes, int n_in,
                              void* d_out, int out_size) {
    const float* x     = (const float*)d_in[0];
    const float* ft    = (const float*)d_in[1];
    const float* h0in  = (const float*)d_in[2];
    const float* c0in  = (const float*)d_in[3];
    const float* w_ih0 = (const float*)d_in[4];
    const float* w_hh0 = (const float*)d_in[5];
    const float* b_ih0 = (const float*)d_in[6];
    const float* b_hh0 = (const float*)d_in[7];
    const float* w_ih1 = (const float*)d_in[8];
    const float* w_hh1 = (const float*)d_in[9];
    const float* b_ih1 = (const float*)d_in[10];
    const float* b_hh1 = (const float*)d_in[11];
    const float* fcw   = (const float*)d_in[12];
    const float* fcb   = (const float*)d_in[13];
    float* out = (float*)d_out;

    cudaFuncSetAttribute(lstm_cell, cudaFuncAttributeMaxDynamicSharedMemorySize, SMEM_B);

    __half *w0p, *w1p, *xp, *ip, *h0p, *h1p;
    float *h1fp, *c0p, *c1p, *b0p, *b1p;
    cudaGetSymbolAddress((void**)&w0p, g_w0);
    cudaGetSymbolAddress((void**)&w1p, g_w1);
    cudaGetSymbolAddress((void**)&xp, g_xp);
    cudaGetSymbolAddress((void**)&ip, g_ip);
    cudaGetSymbolAddress((void**)&h0p, g_h0);
    cudaGetSymbolAddress((void**)&h1p, g_h1);
    cudaGetSymbolAddress((void**)&h1fp, g_h1f);
    cudaGetSymbolAddress((void**)&c0p, g_c0);
    cudaGetSymbolAddress((void**)&c1p, g_c1);
    cudaGetSymbolAddress((void**)&b0p, g_b0);
    cudaGetSymbolAddress((void**)&b1p, g_b1);

    prep_w0<<<(G4 * KTOT0 + 255) / 256, 256>>>(w_ih0, w_hh0);
    prep_w1<<<(G4 * KTOT1 + 255) / 256, 256>>>(w_ih1, w_hh1);
    prep_bias<<<(G4 + 255) / 256, 256>>>(b_ih0, b_hh0, b_ih1, b_hh1);
    prep_xpad<<<(SEQ * BATCH * 64 + 255) / 256, 256>>>(x);
    prep_ipzero<<<(BATCH * 64 + 255) / 256, 256>>>();
    init_state<<<(BATCH * HID + 255) / 256, 256>>>(h0in, c0in);

    const dim3 grid(16, 8);
    const int SN = BATCH * HID;
    int p = 0;

    // encoder
    for (int t = 0; t < SEQ; ++t) {
        lstm_cell<<<grid, CELL_THREADS, SMEM_B>>>(
            xp + (size_t)t * BATCH * 64,
            h0p + p * SN, nullptr,
            w0p, NCH0, b0p, c0p,
            h0p + (p ^ 1) * SN, nullptr);
        lstm_cell<<<grid, CELL_THREADS, SMEM_B>>>(
            nullptr,
            h0p + (p ^ 1) * SN, h1p + p * SN,
            w1p, NCH1, b1p, c1p,
            h1p + (p ^ 1) * SN, (t == SEQ - 1) ? h1fp : nullptr);
        p ^= 1;
    }
    fc_head<<<16, 256>>>(h1fp, fcw, fcb, out, ft);

    // autoregressive decode
    for (int t = 0; t < FUT - 1; ++t) {
        lstm_cell<<<grid, CELL_THREADS, SMEM_B>>>(
            ip,
            h0p + p * SN, nullptr,
            w0p, NCH0, b0p, c0p,
            h0p + (p ^ 1) * SN, nullptr);
        lstm_cell<<<grid, CELL_THREADS, SMEM_B>>>(
            nullptr,
            h0p + (p ^ 1) * SN, h1p + p * SN,
            w1p, NCH1, b1p, c1p,
            h1p + (p ^ 1) * SN, h1fp);
        p ^= 1;
        fc_head<<<16, 256>>>(h1fp, fcw, fcb,
                             out + (size_t)(t + 1) * BATCH * OUT_DIM,
                             (t + 1 < FUT - 1) ? (ft + (size_t)(t + 1) * BATCH * TF_DIM)
                                               : nullptr);
    }
}